// round 15
// baseline (speedup 1.0000x reference)
#include <cuda_runtime.h>
#include <cuda_fp16.h>
#include <stdint.h>

#define B_  4
#define H_  16
#define S_  2048
#define DK_ 64
#define MT  128     // q rows per CTA
#define NTHR 256    // 8 warps, 16 q-rows each
#define ROWH 72     // padded row pitch in halves (144B)

// ---------------- static scratch ----------------
#define NEL ((size_t)B_ * H_ * S_ * DK_)            // 8.4M
__device__ __align__(16) __half g_qh[NEL];
__device__ __align__(16) __half g_kh[NEL];
__device__ __align__(16) __half g_vh[NEL];
__device__ __align__(16) unsigned long long g_maskbits[(size_t)B_ * S_ * (S_ / 64)];
__device__ float g_zinv[B_ * H_ * S_];

// ---------------- helpers ----------------
__device__ __forceinline__ uint32_t pack2(float a, float b) {
    __half2 h = __floats2half2_rn(a, b);
    return *reinterpret_cast<uint32_t*>(&h);
}
__device__ __forceinline__ float ex2(float x) {
    float r;
    asm("ex2.approx.f32 %0, %1;" : "=f"(r) : "f"(x));
    return r;
}
__device__ __forceinline__ void cp16(uint32_t dst, const void* src) {
    asm volatile("cp.async.cg.shared.global [%0], [%1], 16;" :: "r"(dst), "l"(src));
}
#define CP_COMMIT() asm volatile("cp.async.commit_group;" ::: "memory")
#define CP_WAIT0()  asm volatile("cp.async.wait_group 0;" ::: "memory")

#define LDSM4(r, a) \
    asm volatile("ldmatrix.sync.aligned.m8n8.x4.shared.b16 {%0,%1,%2,%3}, [%4];" \
        : "=r"((r)[0]), "=r"((r)[1]), "=r"((r)[2]), "=r"((r)[3]) : "r"(a))
#define LDSM4T(r, a) \
    asm volatile("ldmatrix.sync.aligned.m8n8.x4.trans.shared.b16 {%0,%1,%2,%3}, [%4];" \
        : "=r"((r)[0]), "=r"((r)[1]), "=r"((r)[2]), "=r"((r)[3]) : "r"(a))
#define MMA16816(c, a, b0, b1) \
    asm volatile("mma.sync.aligned.m16n8k16.row.col.f32.f16.f16.f32 " \
        "{%0,%1,%2,%3},{%4,%5,%6,%7},{%8,%9},{%0,%1,%2,%3};" \
        : "+f"((c)[0]), "+f"((c)[1]), "+f"((c)[2]), "+f"((c)[3]) \
        : "r"((a)[0]), "r"((a)[1]), "r"((a)[2]), "r"((a)[3]), "r"(b0), "r"(b1))

// ---- z-kernel smem (halves): Qh | 2 x Kh[64][72] ----
#define Z_KT 64
#define Z_OFF_QH  0
#define Z_OFF_BUF 9216
#define Z_BUF_SZ  4608
#define Z_SMEM_BYTES ((Z_OFF_BUF + 2 * Z_BUF_SZ) * 2)   // 36864 B -> 4 CTAs/SM

// ---- emit-kernel smem (halves): Qh | 2 x {Kh[128][72], Vh[128][72]} ----
#define E_KT 128
#define E_OFF_QH  0
#define E_OFF_BUF 9216
#define E_BUF_SZ  18432        // Kh 9216 + Vh 9216 (128 rows each)
#define E_SMEM_BYTES ((E_OFF_BUF + 2 * E_BUF_SZ) * 2)   // 92160 B -> 2 CTAs/SM

// ================= prep: Q -> fp16 (x 0.125*log2e), K/V -> fp16, mask -> bits ====
__global__ void prep_kernel(const float4* __restrict__ Q, const float4* __restrict__ K,
                            const float4* __restrict__ V, const unsigned int* __restrict__ m)
{
    const int tid = threadIdx.x;
    if (blockIdx.x < 512) {
        const float QSCALE = 0.125f * 1.44269504088896340736f;
        const size_t n = NEL / 4;
        for (size_t i = (size_t)blockIdx.x * 256 + tid; i < n; i += 512 * 256) {
            float4 q = Q[i];
            *(uint2*)(g_qh + 4 * i) = make_uint2(pack2(q.x * QSCALE, q.y * QSCALE),
                                                 pack2(q.z * QSCALE, q.w * QSCALE));
            float4 k = K[i];
            *(uint2*)(g_kh + 4 * i) = make_uint2(pack2(k.x, k.y), pack2(k.z, k.w));
            float4 v = V[i];
            *(uint2*)(g_vh + 4 * i) = make_uint2(pack2(v.x, v.y), pack2(v.z, v.w));
        }
    } else {
        __shared__ int bad01_s, isfloat_s;
        if (tid == 0) { bad01_s = 0; isfloat_s = 1; }
        __syncthreads();
        int bad01 = 0;
        for (int i = tid; i < 4096; i += 256)
            if (m[i] > 1u) bad01 = 1;
        if (bad01) atomicExch(&bad01_s, 1);
        __syncthreads();
        if (bad01_s) {
            int notf = 0;
            for (int i = tid; i < 4096; i += 256) {
                unsigned v = m[i];
                if (v != 0u && v != 0x3F800000u) notf = 1;
            }
            if (notf) atomicExch(&isfloat_s, 0);
        }
        __syncthreads();
        const bool bytemask = bad01_s && !isfloat_s;
        const size_t n = (size_t)B_ * S_ * (S_ / 64);
        for (size_t i = (size_t)(blockIdx.x - 512) * 256 + tid; i < n; i += 512 * 256) {
            unsigned long long bits = 0ull;
            if (bytemask) {
                const uint4* p = (const uint4*)((const unsigned char*)m + i * 64);
                #pragma unroll
                for (int j = 0; j < 4; j++) {
                    uint4 v = p[j];
                    unsigned w[4] = {v.x, v.y, v.z, v.w};
                    #pragma unroll
                    for (int q = 0; q < 4; q++)
                        #pragma unroll
                        for (int bb = 0; bb < 4; bb++)
                            bits |= (unsigned long long)(((w[q] >> (8 * bb)) & 0xffu) == 0u)
                                    << (j * 16 + q * 4 + bb);
                }
            } else {
                const uint4* p = (const uint4*)m + i * 16;
                #pragma unroll
                for (int j = 0; j < 16; j++) {
                    uint4 v = p[j];
                    bits |= ((unsigned long long)(v.x == 0u) << (4 * j))
                          | ((unsigned long long)(v.y == 0u) << (4 * j + 1))
                          | ((unsigned long long)(v.z == 0u) << (4 * j + 2))
                          | ((unsigned long long)(v.w == 0u) << (4 * j + 3));
                }
            }
            g_maskbits[i] = bits;
        }
    }
}

// ================= z-kernel: single-term GEMM1 + masked ex2 -> g_zinv =================
__global__ void __launch_bounds__(NTHR, 4)
z_kernel()
{
    extern __shared__ __half shm[];
    const uint32_t sb = (uint32_t)__cvta_generic_to_shared(shm);

    const int tid = threadIdx.x, wid = tid >> 5, lane = tid & 31;
    const int r = lane >> 2, qc = lane & 3;
    const int m0 = 16 * wid;
    const int arow = lane & 15;
    const int akof = (lane >> 4) << 3;
    const int nlaneK = (lane & 7) + ((lane & 16) >> 1);
    const int klaneK = lane & 8;

    const int q0 = blockIdx.x * MT;
    const size_t bh = (size_t)blockIdx.z * H_ + blockIdx.y;
    const __half* ksrc = g_kh + bh * S_ * DK_;
    const int gr0 = q0 + m0 + r, gr1 = gr0 + 8;
    const unsigned long long* mbp = g_maskbits + (size_t)blockIdx.z * S_ * (S_ / 64);

    {
        const size_t qrow0 = bh * S_ + q0;
        #pragma unroll
        for (int it = 0; it < 4; it++) {
            int i = tid + it * NTHR;
            int row = i >> 3, c8 = i & 7;
            cp16(sb + (Z_OFF_QH + row * ROWH + c8 * 8) * 2,
                 g_qh + (qrow0 + row) * DK_ + c8 * 8);
        }
        #pragma unroll
        for (int it = 0; it < 2; it++) {
            int i = tid + it * NTHR;
            int row = i >> 3, c8 = i & 7;
            cp16(sb + (Z_OFF_BUF + row * ROWH + c8 * 8) * 2, ksrc + (size_t)row * DK_ + c8 * 8);
        }
        CP_COMMIT();
    }

    float z0 = 0.f, z1 = 0.f;
    uint32_t qhi[4][4];

    for (int kt = 0; kt < S_ / Z_KT; kt++) {
        CP_WAIT0();
        __syncthreads();
        if (kt < S_ / Z_KT - 1) {
            const int nb = Z_OFF_BUF + ((kt + 1) & 1) * Z_BUF_SZ;
            const size_t rbase = (size_t)(kt + 1) * Z_KT * DK_;
            #pragma unroll
            for (int it = 0; it < 2; it++) {
                int i = tid + it * NTHR;
                int row = i >> 3, c8 = i & 7;
                cp16(sb + (nb + row * ROWH + c8 * 8) * 2, ksrc + rbase + (size_t)row * DK_ + c8 * 8);
            }
            CP_COMMIT();
        }
        if (kt == 0) {
            #pragma unroll
            for (int s = 0; s < 4; s++)
                LDSM4(qhi[s], sb + (uint32_t)(Z_OFF_QH + (m0 + arow) * ROWH + 16 * s + akof) * 2);
        }

        const uint32_t kh = sb + (Z_OFF_BUF + (kt & 1) * Z_BUF_SZ) * 2;

        float c[8][4];
        #pragma unroll
        for (int j = 0; j < 8; j++)
            #pragma unroll
            for (int k = 0; k < 4; k++) c[j][k] = 0.f;
        #pragma unroll
        for (int s = 0; s < 4; s++) {
            #pragma unroll
            for (int Jp = 0; Jp < 4; Jp++) {
                const uint32_t bo = (uint32_t)((16 * Jp + nlaneK) * ROWH + 16 * s + klaneK) * 2;
                uint32_t kb[4];
                LDSM4(kb, kh + bo);
                MMA16816(c[2 * Jp],     qhi[s], kb[0], kb[1]);
                MMA16816(c[2 * Jp + 1], qhi[s], kb[2], kb[3]);
            }
        }

        const unsigned long long mw0 = mbp[(size_t)gr0 * (S_ / 64) + kt] >> (2 * qc);
        const unsigned long long mw1 = mbp[(size_t)gr1 * (S_ / 64) + kt] >> (2 * qc);
        #pragma unroll
        for (int j = 0; j < 8; j++) {
            z0 += ((mw0 >> (8 * j)) & 1ull)     ? ex2(c[j][0]) : 0.f;
            z0 += ((mw0 >> (8 * j + 1)) & 1ull) ? ex2(c[j][1]) : 0.f;
            z1 += ((mw1 >> (8 * j)) & 1ull)     ? ex2(c[j][2]) : 0.f;
            z1 += ((mw1 >> (8 * j + 1)) & 1ull) ? ex2(c[j][3]) : 0.f;
        }
    }

    z0 += __shfl_xor_sync(0xffffffffu, z0, 1);
    z0 += __shfl_xor_sync(0xffffffffu, z0, 2);
    z1 += __shfl_xor_sync(0xffffffffu, z1, 1);
    z1 += __shfl_xor_sync(0xffffffffu, z1, 2);
    if (qc == 0) {
        g_zinv[bh * S_ + gr0] = 1.0f / z0;
        g_zinv[bh * S_ + gr1] = 1.0f / z1;
    }
}

// ================= emit-kernel: single-term GEMM1 -> attn fp32 + ctx =================
// Scores bit-identical to z_kernel's -> rows of attn sum to exactly 1.
__global__ void __launch_bounds__(NTHR, 2)
emit_kernel(float* __restrict__ ctx_out, float* __restrict__ attn_out)
{
    extern __shared__ __half shm[];
    const uint32_t sb = (uint32_t)__cvta_generic_to_shared(shm);

    const int tid = threadIdx.x, wid = tid >> 5, lane = tid & 31;
    const int r = lane >> 2, qc = lane & 3;
    const int m0 = 16 * wid;
    const int arow = lane & 15;
    const int akof = (lane >> 4) << 3;
    const int nlaneK = (lane & 7) + ((lane & 16) >> 1);
    const int klaneK = lane & 8;
    const int klaneV = lane & 15;
    const int nlaneV = (lane >> 4) << 3;

    const int q0 = blockIdx.x * MT;
    const size_t bh = (size_t)blockIdx.z * H_ + blockIdx.y;
    const size_t kvbase = bh * S_ * DK_;

    const int gr0 = q0 + m0 + r, gr1 = gr0 + 8;
    const unsigned long long* mbp = g_maskbits + (size_t)blockIdx.z * S_ * (S_ / 64);
    const __half* ksrc = g_kh + kvbase;
    const __half* vsrc = g_vh + kvbase;
    float* arow0 = attn_out + (bh * S_ + gr0) * (size_t)S_;
    float* arow1 = attn_out + (bh * S_ + gr1) * (size_t)S_;
    const float zinv0 = g_zinv[bh * S_ + gr0];
    const float zinv1 = g_zinv[bh * S_ + gr1];

    // prologue: Qh + K/V tile 0 (128 rows each)
    {
        const size_t qrow0 = bh * S_ + q0;
        #pragma unroll
        for (int it = 0; it < 4; it++) {
            int i = tid + it * NTHR;           // 128 rows x 8 chunks of Qh
            int row = i >> 3, c8 = i & 7;
            cp16(sb + (E_OFF_QH + row * ROWH + c8 * 8) * 2,
                 g_qh + (qrow0 + row) * DK_ + c8 * 8);
        }
        #pragma unroll
        for (int it = 0; it < 8; it++) {       // {Kh,Vh} x 128 rows x 8 chunks
            int i = tid + it * NTHR;
            int arr = i >> 10, rem = i & 1023, row = rem >> 3, c8 = rem & 7;
            cp16(sb + (E_OFF_BUF + arr * 9216 + row * ROWH + c8 * 8) * 2,
                 (arr ? vsrc : ksrc) + (size_t)row * DK_ + c8 * 8);
        }
        CP_COMMIT();
    }

    float ctx[8][4];
    #pragma unroll
    for (int j = 0; j < 8; j++)
        #pragma unroll
        for (int k = 0; k < 4; k++) ctx[j][k] = 0.f;

    uint32_t qhi[4][4];

    for (int kt = 0; kt < S_ / E_KT; kt++) {
        CP_WAIT0();
        __syncthreads();
        if (kt < S_ / E_KT - 1) {
            const int nb = E_OFF_BUF + ((kt + 1) & 1) * E_BUF_SZ;
            const size_t rbase = (size_t)(kt + 1) * E_KT * DK_;
            #pragma unroll
            for (int it = 0; it < 8; it++) {
                int i = tid + it * NTHR;
                int arr = i >> 10, rem = i & 1023, row = rem >> 3, c8 = rem & 7;
                cp16(sb + (nb + arr * 9216 + row * ROWH + c8 * 8) * 2,
                     (arr ? vsrc : ksrc) + rbase + (size_t)row * DK_ + c8 * 8);
            }
            CP_COMMIT();
        }
        if (kt == 0) {
            #pragma unroll
            for (int s = 0; s < 4; s++)
                LDSM4(qhi[s], sb + (uint32_t)(E_OFF_QH + (m0 + arow) * ROWH + 16 * s + akof) * 2);
        }

        const int bufb = E_OFF_BUF + (kt & 1) * E_BUF_SZ;
        const uint32_t kh = sb + bufb * 2;
        const uint32_t vh = sb + (bufb + 9216) * 2;

        #pragma unroll
        for (int half = 0; half < 2; half++) {
            const int rowoff = half * 64;

            // single-term GEMM1: scores(log2-units) = Qhi * Khi  (== z_kernel scores)
            float c[8][4];
            #pragma unroll
            for (int j = 0; j < 8; j++)
                #pragma unroll
                for (int k = 0; k < 4; k++) c[j][k] = 0.f;
            #pragma unroll
            for (int s = 0; s < 4; s++) {
                #pragma unroll
                for (int Jp = 0; Jp < 4; Jp++) {
                    const uint32_t bo =
                        (uint32_t)((rowoff + 16 * Jp + nlaneK) * ROWH + 16 * s + klaneK) * 2;
                    uint32_t kb[4];
                    LDSM4(kb, kh + bo);
                    MMA16816(c[2 * Jp],     qhi[s], kb[0], kb[1]);
                    MMA16816(c[2 * Jp + 1], qhi[s], kb[2], kb[3]);
                }
            }

            const int mwi = 2 * kt + half;
            const unsigned long long mw0 = mbp[(size_t)gr0 * (S_ / 64) + mwi] >> (2 * qc);
            const unsigned long long mw1 = mbp[(size_t)gr1 * (S_ / 64) + mwi] >> (2 * qc);
            const int colbase = mwi * 64;

            #pragma unroll
            for (int s = 0; s < 4; s++) {
                uint32_t phi[4];
                #pragma unroll
                for (int jj = 0; jj < 2; jj++) {
                    const int j = 2 * s + jj;
                    const int col = 8 * j + 2 * qc;
                    float p00 = ((mw0 >> (8 * j)) & 1ull)     ? ex2(c[j][0]) * zinv0 : 0.f;
                    float p01 = ((mw0 >> (8 * j + 1)) & 1ull) ? ex2(c[j][1]) * zinv0 : 0.f;
                    float p10 = ((mw1 >> (8 * j)) & 1ull)     ? ex2(c[j][2]) * zinv1 : 0.f;
                    float p11 = ((mw1 >> (8 * j + 1)) & 1ull) ? ex2(c[j][3]) * zinv1 : 0.f;
                    __stwt((float2*)(arow0 + colbase + col), make_float2(p00, p01));
                    __stwt((float2*)(arow1 + colbase + col), make_float2(p10, p11));
                    phi[2 * jj]     = pack2(p00, p01);
                    phi[2 * jj + 1] = pack2(p10, p11);
                }
                #pragma unroll
                for (int P = 0; P < 4; P++) {
                    const uint32_t vo =
                        (uint32_t)((rowoff + 16 * s + klaneV) * ROWH + 16 * P + nlaneV) * 2;
                    uint32_t vb[4];
                    LDSM4T(vb, vh + vo);
                    MMA16816(ctx[2 * P],     phi, vb[0], vb[1]);
                    MMA16816(ctx[2 * P + 1], phi, vb[2], vb[3]);
                }
            }
        }
    }

    float* crow0 = ctx_out + (bh * S_ + gr0) * DK_;
    float* crow1 = ctx_out + (bh * S_ + gr1) * DK_;
    #pragma unroll
    for (int j = 0; j < 8; j++) {
        const int col = 8 * j + 2 * qc;
        __stwt((float2*)(crow0 + col), make_float2(ctx[j][0], ctx[j][1]));
        __stwt((float2*)(crow1 + col), make_float2(ctx[j][2], ctx[j][3]));
    }
}

// ---------------- launch ----------------
extern "C" void kernel_launch(void* const* d_in, const int* in_sizes, int n_in,
                              void* d_out, int out_size) {
    (void)in_sizes; (void)n_in; (void)out_size;
    const float* Q = (const float*)d_in[0];
    const float* K = (const float*)d_in[1];
    const float* V = (const float*)d_in[2];
    const void*  mask = d_in[3];

    float* ctx_out  = (float*)d_out;
    float* attn_out = ctx_out + NEL;

    cudaFuncSetAttribute(z_kernel, cudaFuncAttributeMaxDynamicSharedMemorySize, Z_SMEM_BYTES);
    cudaFuncSetAttribute(emit_kernel, cudaFuncAttributeMaxDynamicSharedMemorySize, E_SMEM_BYTES);

    prep_kernel<<<1024, 256>>>((const float4*)Q, (const float4*)K, (const float4*)V,
                               (const unsigned int*)mask);
    dim3 grid(S_ / MT, H_, B_);
    z_kernel<<<grid, NTHR, Z_SMEM_BYTES>>>();
    emit_kernel<<<grid, NTHR, E_SMEM_BYTES>>>(ctx_out, attn_out);
}